// round 11
// baseline (speedup 1.0000x reference)
#include <cuda_runtime.h>
#include <cuda_fp16.h>

// retinex_synthesis: out = clip(expm1(log1p(ins) + blur(log1p(bg) - log1p(ins))), 0, 1)
// blur = depthwise 31x31 Gaussian (sigma=5), separable.
// Algebra:  blur(bg_log)-blur(ins_log) = blur(d2), d2 = log2(1+bg)-log2(1+ins)
//           out = (1+ins) * 2^blur(d2) - 1
// K1: horizontal 31-tap on d2 -> fp16 temp (half2 column pairs). At DRAM floor.
// K2: vertical 31-tap in HFMA2, 2 cols x 32 rows/thread. Weights are fp16
//     broadcast pairs in __constant__ (-> uniform regs, frees vector regs for
//     load batching; R10 held them in ~31 vector regs).

static constexpr int Wd    = 512;
static constexpr int Hd    = 512;
static constexpr int NIMG  = 48;                // B*C = 16*3
static constexpr int NPIX  = NIMG * Hd * Wd;    // 12,582,912
static constexpr int NROWS = NIMG * Hd;         // 24,576

__device__ __align__(16) __half2 g_temp2[NPIX / 2];   // 25.2 MB scratch

// Normalized 1D Gaussian, sigma=5, 31 taps (double-derived fp32 literals).
#define GW_LIST { \
    8.8805900e-4f, 1.5860940e-3f, 2.7217700e-3f, 4.4874400e-3f, 7.1084370e-3f, \
    1.0818768e-2f, 1.5820117e-2f, 2.2226435e-2f, 3.0002550e-2f, 3.8911210e-2f, \
    4.8486353e-2f, 5.8048703e-2f, 6.6771903e-2f, 7.3794366e-2f, 7.8357554e-2f, \
    7.9940482e-2f, \
    7.8357554e-2f, 7.3794366e-2f, 6.6771903e-2f, 5.8048703e-2f, 4.8486353e-2f, \
    3.8911210e-2f, 3.0002550e-2f, 2.2226435e-2f, 1.5820117e-2f, 1.0818768e-2f, \
    7.1084370e-3f, 4.4874400e-3f, 2.7217700e-3f, 1.5860940e-3f, 8.8805900e-4f }

// Same weights as fp16 broadcast pairs (bit patterns, RN-rounded from above).
__constant__ __align__(4) unsigned cw2u[31] = {
    0x13461346u, 0x167F167Fu, 0x19931993u, 0x1C981C98u, 0x1F471F47u,
    0x218A218Au, 0x240D240Du, 0x25B125B1u, 0x27AE27AEu, 0x28FB28FBu,
    0x2A352A35u, 0x2B6E2B6Eu, 0x2C462C46u, 0x2CB92CB9u, 0x2D042D04u,
    0x2D1E2D1Eu,
    0x2D042D04u, 0x2CB92CB9u, 0x2C462C46u, 0x2B6E2B6Eu, 0x2A352A35u,
    0x28FB28FBu, 0x27AE27AEu, 0x25B125B1u, 0x240D240Du, 0x218A218Au,
    0x1F471F47u, 0x1C981C98u, 0x19931993u, 0x167F167Fu, 0x13461346u };

__device__ __forceinline__ __half2 cw2(int k) {       // compile-time k
    union { unsigned u; __half2 h; } c; c.u = cw2u[k]; return c.h;
}
__device__ __forceinline__ float ex2(float x) {        // MUFU.EX2
    float r; asm("ex2.approx.ftz.f32 %0, %1;" : "=f"(r) : "f"(x)); return r;
}
__device__ __forceinline__ float dlog2(float b, float i) {   // log2(1+b)-log2(1+i)
    return __log2f(1.0f + b) - __log2f(1.0f + i);
}
__device__ __forceinline__ unsigned h2u(__half2 h) {
    union { __half2 h; unsigned u; } c; c.h = h; return c.u;
}

// ---------------------------------------------------------------------------
// K1: horizontal blur of d2. One block = 4 rows (2048 floats). UNCHANGED.
// ---------------------------------------------------------------------------
__global__ void __launch_bounds__(256) k_hblur(const float* __restrict__ bg,
                                               const float* __restrict__ ins) {
    const float w[31] = GW_LIST;
    __shared__ __align__(16) float s[4][544];   // [0..15]=0 | data | [528..543]=0

    const int tid = threadIdx.x;
    if (tid < 128) {
        const int r = tid >> 5, p = tid & 31;
        s[r][(p < 16) ? p : (512 + p)] = 0.0f;
    }

    const size_t gb = (size_t)blockIdx.x * 512;         // float4 units
    const float4* bg4 = (const float4*)bg;
    const float4* in4 = (const float4*)ins;

#pragma unroll
    for (int h = 0; h < 2; h++) {
        const int q = tid + h * 256;                    // f4 idx in block: 0..511
        const float4 b = __ldcs(bg4 + gb + q);          // bg: stream, evict-first
        const float4 i = in4[gb + q];                   // ins: keep in L2 for K2
        const int row = q >> 7, col = (q & 127) * 4;
        *(float4*)&s[row][16 + col] =
            make_float4(dlog2(b.x, i.x), dlog2(b.y, i.y),
                        dlog2(b.z, i.z), dlog2(b.w, i.w));
    }
    __syncthreads();

    const int row = tid >> 6;             // 0..3
    const int col = (tid & 63) * 8;       // 0..504

    float v[40];
#pragma unroll
    for (int q = 0; q < 10; q++) {
        const float4 t = *(const float4*)&s[row][col + 4 * q];     // LDS.128
        v[4*q + 0] = t.x; v[4*q + 1] = t.y; v[4*q + 2] = t.z; v[4*q + 3] = t.w;
    }

    float acc[8];
#pragma unroll
    for (int r = 0; r < 8; r++) acc[r] = 0.0f;
#pragma unroll
    for (int j = 1; j < 39; j++) {
#pragma unroll
        for (int r = 0; r < 8; r++) {
            const int k = j - 1 - r;
            if (k >= 0 && k < 31) acc[r] = fmaf(w[k], v[j], acc[r]);
        }
    }

    uint4 u;
    u.x = h2u(__floats2half2_rn(acc[0], acc[1]));
    u.y = h2u(__floats2half2_rn(acc[2], acc[3]));
    u.z = h2u(__floats2half2_rn(acc[4], acc[5]));
    u.w = h2u(__floats2half2_rn(acc[6], acc[7]));
    *(uint4*)((__half*)g_temp2 + ((size_t)blockIdx.x * 4 + row) * Wd + col) = u;
}

// ---------------------------------------------------------------------------
// K2: vertical blur + fused epilogue. Thread = 2 adjacent columns x 32 rows.
// HFMA2, weights from __constant__ (uniform path). GUARD only on edge y-tiles.
// Block 256 threads = full 512-col width; grid = (Hd/32, NIMG).
// ---------------------------------------------------------------------------
template <bool GUARD>
__device__ __forceinline__ void vbody(const float2* __restrict__ ins2,
                                      float2* __restrict__ out2,
                                      int y0, size_t base) {
    __half2 acc[32];
#pragma unroll
    for (int r = 0; r < 32; r++) acc[r] = __half2half2(__ushort_as_half(0));

#pragma unroll
    for (int m = 0; m < 62; m++) {
        const int yy = y0 + m - 15;
        __half2 v;
        if (GUARD && (yy < 0 || yy >= Hd)) v = __half2half2(__ushort_as_half(0));
        else                               v = g_temp2[base + (size_t)yy * 256];
#pragma unroll
        for (int r = 0; r < 32; r++) {
            const int k = m - r;
            if (k >= 0 && k < 31)
                acc[r] = __hfma2(v, cw2(k), acc[r]);
        }
    }

#pragma unroll
    for (int r = 0; r < 32; r++) {
        const float2 a  = __half22float2(acc[r]);
        const float2 iv = ins2[base + (size_t)(y0 + r) * 256];   // plain LDG (L2)
        const float e0 = fmaf(iv.x + 1.0f, ex2(a.x), -1.0f);     // (1+ins)*2^acc-1
        const float e1 = fmaf(iv.y + 1.0f, ex2(a.y), -1.0f);
        float2 o;
        o.x = fminf(fmaxf(e0, 0.0f), 1.0f);
        o.y = fminf(fmaxf(e1, 0.0f), 1.0f);
        out2[base + (size_t)(y0 + r) * 256] = o;
    }
}

__global__ void __launch_bounds__(256, 3) k_vfinal(const float2* __restrict__ ins2,
                                                   float2* __restrict__ out2) {
    const int y0 = blockIdx.x * 32;
    const size_t base = (size_t)blockIdx.y * (Hd * 256) + threadIdx.x;

    if (blockIdx.x == 0 || blockIdx.x == gridDim.x - 1)
        vbody<true >(ins2, out2, y0, base);
    else
        vbody<false>(ins2, out2, y0, base);
}

// ---------------------------------------------------------------------------
extern "C" void kernel_launch(void* const* d_in, const int* in_sizes, int n_in,
                              void* d_out, int out_size) {
    (void)in_sizes; (void)n_in; (void)out_size;
    const float* bg  = (const float*)d_in[0];   // background
    const float* ins = (const float*)d_in[1];   // insatance
    float* out = (float*)d_out;

    k_hblur <<<NROWS / 4, 256>>>(bg, ins);
    k_vfinal<<<dim3(Hd / 32, NIMG), 256>>>((const float2*)ins, (float2*)out);
}

// round 13
// speedup vs baseline: 1.1223x; 1.1223x over previous
#include <cuda_runtime.h>
#include <cuda_fp16.h>

// retinex_synthesis: out = clip(expm1(log1p(ins) + blur(log1p(bg) - log1p(ins))), 0, 1)
// blur = depthwise 31x31 Gaussian (sigma=5), separable.
// Algebra:  blur(bg_log)-blur(ins_log) = blur(d2), d2 = log2(1+bg)-log2(1+ins)
//           out = (1+ins) * 2^blur(d2) - 1
// K1: horizontal 31-tap on d2 -> fp16 temp, stored with an L2::evict_last
//     cache-policy hint (createpolicy + st.global.L2::cache_hint) so the 25 MB
//     temp survives in L2 for K2. bg streamed (__ldcs); ins plain.
// K2: vertical 31-tap in HFMA2 (R10 config exactly: 2 cols x 16 rows/thread),
//     float2 fused epilogue.

static constexpr int Wd    = 512;
static constexpr int Hd    = 512;
static constexpr int NIMG  = 48;                // B*C = 16*3
static constexpr int NPIX  = NIMG * Hd * Wd;    // 12,582,912
static constexpr int NROWS = NIMG * Hd;         // 24,576

__device__ __align__(16) __half2 g_temp2[NPIX / 2];   // 25.2 MB scratch

// Normalized 1D Gaussian, sigma=5, 31 taps (double-derived literals).
#define GW_LIST { \
    8.8805900e-4f, 1.5860940e-3f, 2.7217700e-3f, 4.4874400e-3f, 7.1084370e-3f, \
    1.0818768e-2f, 1.5820117e-2f, 2.2226435e-2f, 3.0002550e-2f, 3.8911210e-2f, \
    4.8486353e-2f, 5.8048703e-2f, 6.6771903e-2f, 7.3794366e-2f, 7.8357554e-2f, \
    7.9940482e-2f, \
    7.8357554e-2f, 7.3794366e-2f, 6.6771903e-2f, 5.8048703e-2f, 4.8486353e-2f, \
    3.8911210e-2f, 3.0002550e-2f, 2.2226435e-2f, 1.5820117e-2f, 1.0818768e-2f, \
    7.1084370e-3f, 4.4874400e-3f, 2.7217700e-3f, 1.5860940e-3f, 8.8805900e-4f }

__device__ __forceinline__ float ex2(float x) {        // MUFU.EX2
    float r; asm("ex2.approx.ftz.f32 %0, %1;" : "=f"(r) : "f"(x)); return r;
}
__device__ __forceinline__ float dlog2(float b, float i) {   // log2(1+b)-log2(1+i)
    return __log2f(1.0f + b) - __log2f(1.0f + i);
}
__device__ __forceinline__ unsigned h2u(__half2 h) {
    union { __half2 h; unsigned u; } c; c.h = h; return c.u;
}

// ---------------------------------------------------------------------------
// K1: horizontal blur of d2. One block = 4 rows (2048 floats).
// ---------------------------------------------------------------------------
__global__ void __launch_bounds__(256) k_hblur(const float* __restrict__ bg,
                                               const float* __restrict__ ins) {
    const float w[31] = GW_LIST;
    __shared__ __align__(16) float s[4][544];   // [0..15]=0 | data | [528..543]=0

    const int tid = threadIdx.x;
    if (tid < 128) {
        const int r = tid >> 5, p = tid & 31;
        s[r][(p < 16) ? p : (512 + p)] = 0.0f;
    }

    const size_t gb = (size_t)blockIdx.x * 512;         // float4 units
    const float4* bg4 = (const float4*)bg;
    const float4* in4 = (const float4*)ins;

#pragma unroll
    for (int h = 0; h < 2; h++) {
        const int q = tid + h * 256;                    // f4 idx in block: 0..511
        const float4 b = __ldcs(bg4 + gb + q);          // bg: stream, evict-first
        const float4 i = in4[gb + q];                   // ins: plain
        const int row = q >> 7, col = (q & 127) * 4;
        *(float4*)&s[row][16 + col] =
            make_float4(dlog2(b.x, i.x), dlog2(b.y, i.y),
                        dlog2(b.z, i.z), dlog2(b.w, i.w));
    }
    __syncthreads();

    const int row = tid >> 6;             // 0..3
    const int col = (tid & 63) * 8;       // 0..504

    float v[40];
#pragma unroll
    for (int q = 0; q < 10; q++) {
        const float4 t = *(const float4*)&s[row][col + 4 * q];     // LDS.128
        v[4*q + 0] = t.x; v[4*q + 1] = t.y; v[4*q + 2] = t.z; v[4*q + 3] = t.w;
    }

    float acc[8];
#pragma unroll
    for (int r = 0; r < 8; r++) acc[r] = 0.0f;
#pragma unroll
    for (int j = 1; j < 39; j++) {
#pragma unroll
        for (int r = 0; r < 8; r++) {
            const int k = j - 1 - r;
            if (k >= 0 && k < 31) acc[r] = fmaf(w[k], v[j], acc[r]);
        }
    }

    uint4 u;
    u.x = h2u(__floats2half2_rn(acc[0], acc[1]));
    u.y = h2u(__floats2half2_rn(acc[2], acc[3]));
    u.z = h2u(__floats2half2_rn(acc[4], acc[5]));
    u.w = h2u(__floats2half2_rn(acc[6], acc[7]));

    // evict-last hinted 128-bit store (policy-descriptor form)
    void* dst = (__half*)g_temp2 + ((size_t)blockIdx.x * 4 + row) * Wd + col;
    unsigned long long pol;
    asm("createpolicy.fractional.L2::evict_last.b64 %0, 1.0;" : "=l"(pol));
    asm volatile("st.global.L2::cache_hint.v4.b32 [%0], {%1,%2,%3,%4}, %5;"
                 :: "l"(dst), "r"(u.x), "r"(u.y), "r"(u.z), "r"(u.w), "l"(pol)
                 : "memory");
}

// ---------------------------------------------------------------------------
// K2: vertical blur + fused epilogue. EXACT R10 config (best measured K2).
// Thread = 2 adjacent columns x 16 rows. HFMA2 with reg-pair fp16 weights.
// ---------------------------------------------------------------------------
template <bool GUARD>
__device__ __forceinline__ void vbody(const float2* __restrict__ ins2,
                                      float2* __restrict__ out2,
                                      int y0, size_t base) {
    const float w[31] = GW_LIST;

    __half2 acc[16];
#pragma unroll
    for (int r = 0; r < 16; r++) acc[r] = __half2half2(__ushort_as_half(0));

#pragma unroll
    for (int m = 0; m < 46; m++) {
        const int yy = y0 + m - 15;
        __half2 v;
        if (GUARD && (yy < 0 || yy >= Hd)) v = __half2half2(__ushort_as_half(0));
        else                               v = g_temp2[base + (size_t)yy * 256];
#pragma unroll
        for (int r = 0; r < 16; r++) {
            const int k = m - r;
            if (k >= 0 && k < 31)
                acc[r] = __hfma2(v, __floats2half2_rn(w[k], w[k]), acc[r]);
        }
    }

#pragma unroll
    for (int r = 0; r < 16; r++) {
        const float2 a  = __half22float2(acc[r]);
        const float2 iv = ins2[base + (size_t)(y0 + r) * 256];   // plain LDG
        const float e0 = fmaf(iv.x + 1.0f, ex2(a.x), -1.0f);     // (1+ins)*2^acc-1
        const float e1 = fmaf(iv.y + 1.0f, ex2(a.y), -1.0f);
        float2 o;
        o.x = fminf(fmaxf(e0, 0.0f), 1.0f);
        o.y = fminf(fmaxf(e1, 0.0f), 1.0f);
        out2[base + (size_t)(y0 + r) * 256] = o;
    }
}

__global__ void __launch_bounds__(256, 4) k_vfinal(const float2* __restrict__ ins2,
                                                   float2* __restrict__ out2) {
    const int y0 = blockIdx.x * 16;
    const size_t base = (size_t)blockIdx.y * (Hd * 256) + threadIdx.x;

    if (blockIdx.x == 0 || blockIdx.x == gridDim.x - 1)
        vbody<true >(ins2, out2, y0, base);
    else
        vbody<false>(ins2, out2, y0, base);
}

// ---------------------------------------------------------------------------
extern "C" void kernel_launch(void* const* d_in, const int* in_sizes, int n_in,
                              void* d_out, int out_size) {
    (void)in_sizes; (void)n_in; (void)out_size;
    const float* bg  = (const float*)d_in[0];   // background
    const float* ins = (const float*)d_in[1];   // insatance
    float* out = (float*)d_out;

    k_hblur <<<NROWS / 4, 256>>>(bg, ins);
    k_vfinal<<<dim3(Hd / 16, NIMG), 256>>>((const float2*)ins, (float2*)out);
}

// round 14
// speedup vs baseline: 1.1231x; 1.0007x over previous
#include <cuda_runtime.h>
#include <cuda_fp16.h>

// retinex_synthesis: out = clip(expm1(log1p(ins) + blur(log1p(bg) - log1p(ins))), 0, 1)
// blur = depthwise 31x31 Gaussian (sigma=5), separable.
// Algebra:  blur(bg_log)-blur(ins_log) = blur(d2), d2 = log2(1+bg)-log2(1+ins)
//           out = (1+ins) * 2^blur(d2) - 1
// K1: horizontal 31-tap on d2 -> fp16 temp (evict-last hinted stores).
// K2: vertical 31-tap in HFMA2. The 46x512 fp16 temp slab is STAGED IN SMEM
//     via 12 independent uint4 loads/thread (latency decoupled from regs),
//     then conflict-free LDS feeds the conv. Edge zero-pad in staging loop.

static constexpr int Wd    = 512;
static constexpr int Hd    = 512;
static constexpr int NIMG  = 48;                // B*C = 16*3
static constexpr int NPIX  = NIMG * Hd * Wd;    // 12,582,912
static constexpr int NROWS = NIMG * Hd;         // 24,576

__device__ __align__(16) __half2 g_temp2[NPIX / 2];   // 25.2 MB scratch

// Normalized 1D Gaussian, sigma=5, 31 taps (double-derived literals).
#define GW_LIST { \
    8.8805900e-4f, 1.5860940e-3f, 2.7217700e-3f, 4.4874400e-3f, 7.1084370e-3f, \
    1.0818768e-2f, 1.5820117e-2f, 2.2226435e-2f, 3.0002550e-2f, 3.8911210e-2f, \
    4.8486353e-2f, 5.8048703e-2f, 6.6771903e-2f, 7.3794366e-2f, 7.8357554e-2f, \
    7.9940482e-2f, \
    7.8357554e-2f, 7.3794366e-2f, 6.6771903e-2f, 5.8048703e-2f, 4.8486353e-2f, \
    3.8911210e-2f, 3.0002550e-2f, 2.2226435e-2f, 1.5820117e-2f, 1.0818768e-2f, \
    7.1084370e-3f, 4.4874400e-3f, 2.7217700e-3f, 1.5860940e-3f, 8.8805900e-4f }

__device__ __forceinline__ float ex2(float x) {        // MUFU.EX2
    float r; asm("ex2.approx.ftz.f32 %0, %1;" : "=f"(r) : "f"(x)); return r;
}
__device__ __forceinline__ float dlog2(float b, float i) {   // log2(1+b)-log2(1+i)
    return __log2f(1.0f + b) - __log2f(1.0f + i);
}
__device__ __forceinline__ unsigned h2u(__half2 h) {
    union { __half2 h; unsigned u; } c; c.h = h; return c.u;
}

// ---------------------------------------------------------------------------
// K1: horizontal blur of d2. One block = 4 rows (2048 floats). R13 version.
// ---------------------------------------------------------------------------
__global__ void __launch_bounds__(256) k_hblur(const float* __restrict__ bg,
                                               const float* __restrict__ ins) {
    const float w[31] = GW_LIST;
    __shared__ __align__(16) float s[4][544];   // [0..15]=0 | data | [528..543]=0

    const int tid = threadIdx.x;
    if (tid < 128) {
        const int r = tid >> 5, p = tid & 31;
        s[r][(p < 16) ? p : (512 + p)] = 0.0f;
    }

    const size_t gb = (size_t)blockIdx.x * 512;         // float4 units
    const float4* bg4 = (const float4*)bg;
    const float4* in4 = (const float4*)ins;

#pragma unroll
    for (int h = 0; h < 2; h++) {
        const int q = tid + h * 256;                    // f4 idx in block: 0..511
        const float4 b = __ldcs(bg4 + gb + q);          // bg: stream, evict-first
        const float4 i = in4[gb + q];                   // ins: plain
        const int row = q >> 7, col = (q & 127) * 4;
        *(float4*)&s[row][16 + col] =
            make_float4(dlog2(b.x, i.x), dlog2(b.y, i.y),
                        dlog2(b.z, i.z), dlog2(b.w, i.w));
    }
    __syncthreads();

    const int row = tid >> 6;             // 0..3
    const int col = (tid & 63) * 8;       // 0..504

    float v[40];
#pragma unroll
    for (int q = 0; q < 10; q++) {
        const float4 t = *(const float4*)&s[row][col + 4 * q];     // LDS.128
        v[4*q + 0] = t.x; v[4*q + 1] = t.y; v[4*q + 2] = t.z; v[4*q + 3] = t.w;
    }

    float acc[8];
#pragma unroll
    for (int r = 0; r < 8; r++) acc[r] = 0.0f;
#pragma unroll
    for (int j = 1; j < 39; j++) {
#pragma unroll
        for (int r = 0; r < 8; r++) {
            const int k = j - 1 - r;
            if (k >= 0 && k < 31) acc[r] = fmaf(w[k], v[j], acc[r]);
        }
    }

    uint4 u;
    u.x = h2u(__floats2half2_rn(acc[0], acc[1]));
    u.y = h2u(__floats2half2_rn(acc[2], acc[3]));
    u.z = h2u(__floats2half2_rn(acc[4], acc[5]));
    u.w = h2u(__floats2half2_rn(acc[6], acc[7]));

    // evict-last hinted 128-bit store (policy-descriptor form)
    void* dst = (__half*)g_temp2 + ((size_t)blockIdx.x * 4 + row) * Wd + col;
    unsigned long long pol;
    asm("createpolicy.fractional.L2::evict_last.b64 %0, 1.0;" : "=l"(pol));
    asm volatile("st.global.L2::cache_hint.v4.b32 [%0], {%1,%2,%3,%4}, %5;"
                 :: "l"(dst), "r"(u.x), "r"(u.y), "r"(u.z), "r"(u.w), "l"(pol)
                 : "memory");
}

// ---------------------------------------------------------------------------
// K2: vertical blur + fused epilogue, smem-staged.
// Block = 16 out rows x 512 cols. Stage rows [y0-15, y0+30] (46 rows, zero-
// padded at image edges) into smem, then HFMA2 conv from LDS.
// grid = (Hd/16, NIMG), 256 threads (thread = 2 adjacent cols x 16 rows).
// ---------------------------------------------------------------------------
static constexpr int SROWS = 46;

__global__ void __launch_bounds__(256) k_vfinal(const float2* __restrict__ ins2,
                                                float2* __restrict__ out2) {
    const float w[31] = GW_LIST;
    __shared__ __align__(16) __half2 s2[SROWS][256];   // 47104 B

    const int tid = threadIdx.x;
    const int y0  = blockIdx.x * 16;
    const int z   = blockIdx.y;
    const size_t base = (size_t)z * (Hd * 256) + tid;   // half2/float2 units

    // ---- stage 46 rows of temp into smem (12 independent uint4 loads) ----
    const __half* tp = (const __half*)g_temp2 + (size_t)z * (Hd * Wd);
#pragma unroll
    for (int it = 0; it < 12; it++) {
        const int c = tid + it * 256;          // uint4 chunk id, 64 per row
        if (c < SROWS * 64) {
            const int m   = c >> 6;
            const int col = c & 63;            // uint4 within row
            const int yy  = y0 + m - 15;
            uint4 val = make_uint4(0u, 0u, 0u, 0u);
            if (yy >= 0 && yy < Hd)
                val = *(const uint4*)(tp + (size_t)yy * Wd + col * 8);
            *(uint4*)&s2[m][col * 4] = val;
        }
    }
    __syncthreads();

    // ---- vertical 31-tap conv from smem (conflict-free LDS.32) ----
    __half2 acc[16];
#pragma unroll
    for (int r = 0; r < 16; r++) acc[r] = __half2half2(__ushort_as_half(0));

#pragma unroll
    for (int m = 0; m < SROWS; m++) {
        const __half2 v = s2[m][tid];
#pragma unroll
        for (int r = 0; r < 16; r++) {
            const int k = m - r;
            if (k >= 0 && k < 31)
                acc[r] = __hfma2(v, __floats2half2_rn(w[k], w[k]), acc[r]);
        }
    }

    // ---- fused epilogue: out = clamp((1+ins) * 2^acc - 1) ----
#pragma unroll
    for (int r = 0; r < 16; r++) {
        const float2 a  = __half22float2(acc[r]);
        const float2 iv = ins2[base + (size_t)(y0 + r) * 256];   // plain LDG
        const float e0 = fmaf(iv.x + 1.0f, ex2(a.x), -1.0f);
        const float e1 = fmaf(iv.y + 1.0f, ex2(a.y), -1.0f);
        float2 o;
        o.x = fminf(fmaxf(e0, 0.0f), 1.0f);
        o.y = fminf(fmaxf(e1, 0.0f), 1.0f);
        out2[base + (size_t)(y0 + r) * 256] = o;
    }
}

// ---------------------------------------------------------------------------
extern "C" void kernel_launch(void* const* d_in, const int* in_sizes, int n_in,
                              void* d_out, int out_size) {
    (void)in_sizes; (void)n_in; (void)out_size;
    const float* bg  = (const float*)d_in[0];   // background
    const float* ins = (const float*)d_in[1];   // insatance
    float* out = (float*)d_out;

    k_hblur <<<NROWS / 4, 256>>>(bg, ins);
    k_vfinal<<<dim3(Hd / 16, NIMG), 256>>>((const float2*)ins, (float2*)out);
}